// round 6
// baseline (speedup 1.0000x reference)
#include <cuda_runtime.h>

#define Nn   1024
#define Cc   64
#define HID  128
#define TS   16                         // output sub-tile edge
#define NTS  (Nn / TS)                  // 64
#define NUNITS (NTS * (NTS + 1) / 2)    // 2080

// interleaved: g_p[h*Nn + n] = (pi[h,n], pj[h,n])
__device__ float2 g_p[HID * Nn];

__device__ __forceinline__ float tanh_apx(float x) {
    float y;
    asm("tanh.approx.f32 %0, %1;" : "=f"(y) : "f"(x));
    return y;
}

// ---------------------------------------------------------------------------
// prep: pi[h,n] = sum_c W1[h,Cc+c]*tanh(x[c,n]) + b1[h]
//       pj[h,n] = sum_c W1[h,   c]*tanh(x[c,n])
// grid 256 blocks x 256 threads; block = 4-col n chunk;
// thread = (h = tid&127, 2 cols selected by tid>>7). Short critical path.
// ---------------------------------------------------------------------------
#define NCH 4
__global__ __launch_bounds__(256) void prep_kernel(const float* __restrict__ x,
                                                   const float* __restrict__ W1,
                                                   const float* __restrict__ b1) {
    __shared__ float t_s[Cc][NCH];
    const int n0  = blockIdx.x * NCH;
    const int tid = threadIdx.x;

    if (tid < Cc * NCH) {
        int c = tid / NCH, n = tid % NCH;
        t_s[c][n] = tanhf(x[c * Nn + n0 + n]);   // precise tanh in pre-pass
    }
    __syncthreads();

    const int h  = tid & 127;
    const int ng = (tid >> 7) * 2;     // 0 or 2
    float accj0 = 0.f, accj1 = 0.f;
    const float bb = b1[h];
    float acci0 = bb, acci1 = bb;

#pragma unroll
    for (int c = 0; c < Cc; c++) {
        float wj = W1[h * (2 * Cc) + c];
        float wi = W1[h * (2 * Cc) + Cc + c];
        float t0 = t_s[c][ng + 0];
        float t1 = t_s[c][ng + 1];
        accj0 = fmaf(wj, t0, accj0);
        acci0 = fmaf(wi, t0, acci0);
        accj1 = fmaf(wj, t1, accj1);
        acci1 = fmaf(wi, t1, acci1);
    }
    g_p[h * Nn + n0 + ng + 0] = make_float2(acci0, accj0);
    g_p[h * Nn + n0 + ng + 1] = make_float2(acci1, accj1);
}

// ---------------------------------------------------------------------------
// pair (exact R3 winner): triangular unit (a <= b), 256 threads,
// thread owns one (i,j):
//   v = sum_h w2[h]*(tanh(pi_i + pj_j) + tanh(pi_j + pj_i)) + 2*b2
// writes out[i,j] and out[j,i].
// ---------------------------------------------------------------------------
__global__ __launch_bounds__(256) void pair_kernel(const float* __restrict__ W2,
                                                   const float* __restrict__ b2,
                                                   float* __restrict__ out) {
    __shared__ __align__(16) float2 pS[HID][2 * TS];   // [h][0..15]=i cols, [16..31]=j cols
    __shared__ float w2s[HID];

    // triangular decode
    int rem = blockIdx.x, a = 0, len = NTS;
    while (rem >= len) { rem -= len; a++; len--; }
    const int b  = a + rem;
    const int i0 = a * TS, j0 = b * TS;

    const int tid = threadIdx.x;
    if (tid < HID) w2s[tid] = W2[tid];

    // stage: 128 h x (16 i-cols + 16 j-cols) float2, as float4 (2 float2 each)
    for (int t = tid; t < HID * 16; t += 256) {
        int h    = t >> 4;
        int q    = t & 15;
        int side = q >> 3;            // 0 = i-side, 1 = j-side
        int c    = (q & 7) * 2;       // float2 column offset
        int src  = side ? j0 : i0;
        float4 v = *(const float4*)&g_p[h * Nn + src + c];
        *(float4*)&pS[h][side * TS + c] = v;
    }
    __syncthreads();

    const int ii = tid >> 4;      // 0..15
    const int jj = tid & 15;      // 0..15

    float acc1 = 0.0f, acc2 = 0.0f;
#pragma unroll 8
    for (int h = 0; h < HID; h++) {
        float2 ai = pS[h][ii];          // (pi_i, pj_i)
        float2 aj = pS[h][TS + jj];     // (pi_j, pj_j)
        float  w  = w2s[h];
        acc1 = fmaf(w, tanh_apx(ai.x + aj.y), acc1);   // e[i,j]
        acc2 = fmaf(w, tanh_apx(aj.x + ai.y), acc2);   // e[j,i]
    }

    const float v  = acc1 + acc2 + 2.0f * b2[0];
    const int gi = i0 + ii, gj = j0 + jj;
    out[gi * Nn + gj] = v;
    out[gj * Nn + gi] = v;     // mirror (same value by construction)
}

extern "C" void kernel_launch(void* const* d_in, const int* in_sizes, int n_in,
                              void* d_out, int out_size) {
    const float* x  = (const float*)d_in[0];
    const float* W1 = (const float*)d_in[1];
    const float* b1 = (const float*)d_in[2];
    const float* W2 = (const float*)d_in[3];
    const float* b2 = (const float*)d_in[4];
    float* out = (float*)d_out;

    prep_kernel<<<Nn / NCH, 256>>>(x, W1, b1);
    pair_kernel<<<NUNITS, 256>>>(W2, b2, out);
}